// round 8
// baseline (speedup 1.0000x reference)
#include <cuda_runtime.h>

// HN=10, ND=40, HF=8 (fixed). A_ENC: agg[j]=sum x[4j-3..4j+2 mod 40].
// A_PRED: agg2[d]=z1[d]+w*(z1[d-1]+z1[d+1]), w=exp(-1/9).
// A_DEC per grid i (m=i%4): m0:s[c]; m1,m2:s[c]+s[c+1]; m3:s[c+1]  (c=i/4, wrap mod 10)
//
// Decomposition: one lane per (element, node): lane L = 10*e + j.
// All global accesses (x,z,y,out) are float4/32B contiguous across lanes.
// Shared memory only for node-ring exchanges (t1, z1 neighbors, s).

typedef unsigned long long u64;

__device__ __forceinline__ u64 pk2(float a, float b) {
    u64 r; asm("mov.b64 %0, {%1, %2};" : "=l"(r) : "f"(a), "f"(b)); return r;
}
__device__ __forceinline__ void upk2(u64 v, float& a, float& b) {
    asm("mov.b64 {%0, %1}, %2;" : "=f"(a), "=f"(b) : "l"(v));
}
__device__ __forceinline__ u64 ffma2(u64 a, u64 b, u64 c) {
    u64 d; asm("fma.rn.f32x2 %0, %1, %2, %3;" : "=l"(d) : "l"(a), "l"(b), "l"(c)); return d;
}
__device__ __forceinline__ u64 add2(u64 a, u64 b) {
    u64 d; asm("add.rn.f32x2 %0, %1, %2;" : "=l"(d) : "l"(a), "l"(b)); return d;
}

struct CW {
    u64 encW[8][4];   // [g][f2] = (enc_root_w[2f2][g], enc_root_w[2f2+1][g])
    u64 encRW[4];     // enc_rel_w pairs
    u64 encB[4];      // enc_rel_b pairs
    u64 W1[8][4];     // (pred_rel_w + pred_root_w) pairs
    u64 W2[8][4];     // (exp(-1/9) * pred_rel_w) pairs
    u64 predB[4];     // pred_rel_b pairs
    float drw[8];     // dec_rel_w
    float dec2[2];    // dec_rel_b, dec_root_w
};
__constant__ CW c_w;
__device__ CW g_stage;

__global__ void prep_kernel(const float* __restrict__ erw, const float* __restrict__ erb,
                            const float* __restrict__ erow,
                            const float* __restrict__ prw, const float* __restrict__ prb,
                            const float* __restrict__ prow,
                            const float* __restrict__ drw, const float* __restrict__ drb,
                            const float* __restrict__ droot) {
    const int t = threadIdx.x;
    const float wE = expf(-1.0f / 9.0f);
    if (t < 32) {
        const int g = t & 7, f2 = t >> 3;
        const int i0 = (2 * f2) * 8 + g;
        const int i1 = (2 * f2 + 1) * 8 + g;
        g_stage.encW[g][f2] = pk2(erow[i0], erow[i1]);
        g_stage.W1[g][f2]   = pk2(prw[i0] + prow[i0], prw[i1] + prow[i1]);
        g_stage.W2[g][f2]   = pk2(wE * prw[i0], wE * prw[i1]);
    }
    if (t < 4) {
        g_stage.encRW[t] = pk2(erw[2 * t], erw[2 * t + 1]);
        g_stage.encB[t]  = pk2(erb[2 * t], erb[2 * t + 1]);
        g_stage.predB[t] = pk2(prb[2 * t], prb[2 * t + 1]);
    }
    if (t < 8) g_stage.drw[t] = drw[t];
    if (t == 0) { g_stage.dec2[0] = drb[0]; g_stage.dec2[1] = droot[0]; }
}

// Per-lane shared slot: 7 u64 (u64 idx 7L+0..3 = z1 exchange; word 14L+8 = t1/agg, later s).
// 7 coprime 16 -> LDS.64/STS.64 bank-pair conflict-free across 16-lane phases.
#define NTHR 320

__global__ __launch_bounds__(NTHR, 3)
void gnn_kernel(const float* __restrict__ x, const float* __restrict__ z,
                const float* __restrict__ y, float* __restrict__ out) {
    __shared__ u64 sm[NTHR * 7];
    float* smf = (float*)sm;

    const int t = threadIdx.x;
    const int j = t % 10;
    const int lane_p = t - j + ((j == 9) ? 0 : j + 1);   // same element, node j+1
    const int lane_m = t - j + ((j == 0) ? 9 : j - 1);   // same element, node j-1
    const long long base = (long long)blockIdx.x * NTHR + t;

    // ---- Fully coalesced loads: own x chunk + own z row ----
    const float4 xv = ((const float4*)x)[base];
    const float4 za = ((const float4*)z)[2 * base];
    const float4 zb = ((const float4*)z)[2 * base + 1];

    // ---- Encoder aggregation via ring exchange of t1 ----
    // t1(chunk j) = y+z+w needed by node j+1; t2 own = x+y+z.
    smf[14 * lane_p + 8] = xv.y + xv.z + xv.w;
    __syncthreads();
    const float agg = smf[14 * t + 8] + (xv.x + xv.y + xv.z);

    // ======== Stage A: z1[f] = relu(agg*erw[f] + erb[f] + sum_g z[g]*erow[f][g]) ====
    u64 acc[4];
    {
        const u64 ab = pk2(agg, agg);
#pragma unroll
        for (int f2 = 0; f2 < 4; f2++)
            acc[f2] = ffma2(ab, c_w.encRW[f2], c_w.encB[f2]);
    }
    const float zf[8] = {za.x, za.y, za.z, za.w, zb.x, zb.y, zb.z, zb.w};
#pragma unroll 1
    for (int p = 0; p < 4; p++) {
        u64 w0[4], w1[4];
#pragma unroll
        for (int f2 = 0; f2 < 4; f2++) {
            w0[f2] = c_w.encW[2 * p][f2];
            w1[f2] = c_w.encW[2 * p + 1][f2];
        }
        const u64 b0 = pk2(zf[2 * p], zf[2 * p]);
        const u64 b1 = pk2(zf[2 * p + 1], zf[2 * p + 1]);
#pragma unroll
        for (int f2 = 0; f2 < 4; f2++) {
            acc[f2] = ffma2(b0, w0[f2], acc[f2]);
            acc[f2] = ffma2(b1, w1[f2], acc[f2]);
        }
    }
    // relu + pack; publish z1 to shared (own slot; doesn't touch others' agg slots)
    u64 z1[4];
#pragma unroll
    for (int k = 0; k < 4; k++) {
        float a, b; upk2(acc[k], a, b);
        z1[k] = pk2(fmaxf(a, 0.0f), fmaxf(b, 0.0f));
        sm[7 * t + k] = z1[k];
    }
    __syncthreads();

    // ---- Fetch ring neighbors' z1 ----
    float z1f[8], uf[8];
#pragma unroll
    for (int k = 0; k < 4; k++) {
        const u64 u = add2(sm[7 * lane_m + k], sm[7 * lane_p + k]);
        upk2(u, uf[2 * k], uf[2 * k + 1]);
        upk2(z1[k], z1f[2 * k], z1f[2 * k + 1]);
    }

    // ======== Stage B: z2 = relu(z1@W1^T + (z1m+z1p)@W2^T + prb); s = z2.drw ========
    u64 acc2[4];
#pragma unroll
    for (int f2 = 0; f2 < 4; f2++) acc2[f2] = c_w.predB[f2];
#pragma unroll 1
    for (int p = 0; p < 4; p++) {
        u64 a0[4], a1[4], c0[4], c1[4];
#pragma unroll
        for (int f2 = 0; f2 < 4; f2++) {
            a0[f2] = c_w.W1[2 * p][f2];
            a1[f2] = c_w.W1[2 * p + 1][f2];
            c0[f2] = c_w.W2[2 * p][f2];
            c1[f2] = c_w.W2[2 * p + 1][f2];
        }
        const u64 bz0 = pk2(z1f[2 * p], z1f[2 * p]);
        const u64 bz1 = pk2(z1f[2 * p + 1], z1f[2 * p + 1]);
        const u64 bu0 = pk2(uf[2 * p], uf[2 * p]);
        const u64 bu1 = pk2(uf[2 * p + 1], uf[2 * p + 1]);
#pragma unroll
        for (int f2 = 0; f2 < 4; f2++) {
            u64 a = acc2[f2];
            a = ffma2(bz0, a0[f2], a);
            a = ffma2(bz1, a1[f2], a);
            a = ffma2(bu0, c0[f2], a);
            a = ffma2(bu1, c1[f2], a);
            acc2[f2] = a;
        }
    }
    float s;
    {
        float f0, f1, f2v, f3, f4v, f5, f6, f7;
        upk2(acc2[0], f0, f1);
        upk2(acc2[1], f2v, f3);
        upk2(acc2[2], f4v, f5);
        upk2(acc2[3], f6, f7);
        s = fmaxf(f0, 0.0f) * c_w.drw[0] + fmaxf(f1, 0.0f) * c_w.drw[1]
          + fmaxf(f2v, 0.0f) * c_w.drw[2] + fmaxf(f3, 0.0f) * c_w.drw[3]
          + fmaxf(f4v, 0.0f) * c_w.drw[4] + fmaxf(f5, 0.0f) * c_w.drw[5]
          + fmaxf(f6, 0.0f) * c_w.drw[6] + fmaxf(f7, 0.0f) * c_w.drw[7];
    }

    // ---- s ring exchange (reuses the agg word; agg reads long done) ----
    __syncthreads();                  // all z1 reads complete before s overwrites region
    smf[14 * t + 8] = s;
    __syncthreads();
    const float sp = smf[14 * lane_p + 8];

    // ---- Output chunk j: fully coalesced ----
    const float4 yv = ((const float4*)y)[base];
    const float drbv   = c_w.dec2[0];
    const float drootv = c_w.dec2[1];
    float4 o;
    const float both = s + sp + drbv;
    o.x = s + drbv + yv.x * drootv;          // m=0
    o.y = both + yv.y * drootv;              // m=1
    o.z = both + yv.z * drootv;              // m=2
    o.w = sp + drbv + yv.w * drootv;         // m=3
    ((float4*)out)[base] = o;
}

extern "C" void kernel_launch(void* const* d_in, const int* in_sizes, int n_in,
                              void* d_out, int out_size) {
    const float* x     = (const float*)d_in[0];
    const float* z     = (const float*)d_in[1];
    const float* y     = (const float*)d_in[2];
    const float* erw   = (const float*)d_in[3];
    const float* erb   = (const float*)d_in[4];
    const float* erow  = (const float*)d_in[5];
    const float* prw   = (const float*)d_in[6];
    const float* prb   = (const float*)d_in[7];
    const float* prow  = (const float*)d_in[8];
    const float* drw   = (const float*)d_in[9];
    const float* drb   = (const float*)d_in[10];
    const float* droot = (const float*)d_in[11];

    const int B = in_sizes[0] / 40;            // 524288
    const int blocks = (B * 10) / NTHR;        // 16384

    prep_kernel<<<1, 32>>>(erw, erb, erow, prw, prb, prow, drw, drb, droot);

    void* stage_ptr = nullptr;
    cudaGetSymbolAddress(&stage_ptr, g_stage);
    cudaMemcpyToSymbolAsync(c_w, stage_ptr, sizeof(CW), 0, cudaMemcpyDeviceToDevice);

    gnn_kernel<<<blocks, NTHR>>>(x, z, y, (float*)d_out);
}

// round 9
// speedup vs baseline: 1.1893x; 1.1893x over previous
#include <cuda_runtime.h>

// HN=10, ND=40, HF=8 (fixed). A_ENC: agg[j]=sum x[4j-3..4j+2 mod 40].
// A_PRED: agg2[d]=z1[d]+w*(z1[d-1]+z1[d+1]), w=exp(-1/9).
// A_DEC per grid i (m=i%4): m0:s[c]; m1,m2:s[c]+s[c+1]; m3:s[c+1]  (c=i/4, wrap mod 10)
//
// R9 = R5 (best kernel: per-element threads, constant-bank weights, 41-stride z1)
//      + cross-block L2 prefetch: block b prefetches tiles of block b+592 (one
//      wave ahead) during its compute phase, keeping DRAM streaming while the
//      chip's blocks are in their synchronized compute phases.

typedef unsigned long long u64;

__device__ __forceinline__ u64 pk2(float a, float b) {
    u64 r; asm("mov.b64 %0, {%1, %2};" : "=l"(r) : "f"(a), "f"(b)); return r;
}
__device__ __forceinline__ void upk2(u64 v, float& a, float& b) {
    asm("mov.b64 {%0, %1}, %2;" : "=f"(a), "=f"(b) : "l"(v));
}
__device__ __forceinline__ u64 ffma2(u64 a, u64 b, u64 c) {
    u64 d; asm("fma.rn.f32x2 %0, %1, %2, %3;" : "=l"(d) : "l"(a), "l"(b), "l"(c)); return d;
}
__device__ __forceinline__ u64 add2(u64 a, u64 b) {
    u64 d; asm("add.rn.f32x2 %0, %1, %2;" : "=l"(d) : "l"(a), "l"(b)); return d;
}
__device__ __forceinline__ void pfL2(const void* p) {
    asm volatile("prefetch.global.L2 [%0];" :: "l"(p));
}

struct CW {
    u64 encW[8][4];   // [g][f2] = (enc_root_w[2f2][g], enc_root_w[2f2+1][g])
    u64 encRW[4];     // enc_rel_w pairs
    u64 encB[4];      // enc_rel_b pairs
    u64 W1[8][4];     // (pred_rel_w + pred_root_w) pairs
    u64 W2[8][4];     // (exp(-1/9) * pred_rel_w) pairs
    u64 predB[4];     // pred_rel_b pairs
    float drw[8];     // dec_rel_w
    float dec2[2];    // dec_rel_b, dec_root_w
};
__constant__ CW c_w;
__device__ CW g_stage;

__global__ void prep_kernel(const float* __restrict__ erw, const float* __restrict__ erb,
                            const float* __restrict__ erow,
                            const float* __restrict__ prw, const float* __restrict__ prb,
                            const float* __restrict__ prow,
                            const float* __restrict__ drw, const float* __restrict__ drb,
                            const float* __restrict__ droot) {
    const int t = threadIdx.x;
    const float wE = expf(-1.0f / 9.0f);
    if (t < 32) {
        const int g = t & 7, f2 = t >> 3;
        const int i0 = (2 * f2) * 8 + g;
        const int i1 = (2 * f2 + 1) * 8 + g;
        g_stage.encW[g][f2] = pk2(erow[i0], erow[i1]);
        g_stage.W1[g][f2]   = pk2(prw[i0] + prow[i0], prw[i1] + prow[i1]);
        g_stage.W2[g][f2]   = pk2(wE * prw[i0], wE * prw[i1]);
    }
    if (t < 4) {
        g_stage.encRW[t] = pk2(erw[2 * t], erw[2 * t + 1]);
        g_stage.encB[t]  = pk2(erb[2 * t], erb[2 * t + 1]);
        g_stage.predB[t] = pk2(prb[2 * t], prb[2 * t + 1]);
    }
    if (t < 8) g_stage.drw[t] = drw[t];
    if (t == 0) { g_stage.dec2[0] = drb[0]; g_stage.dec2[1] = droot[0]; }
}

// Shared: buf float4[128*21] (x transient as [128][11] f4, then z; z1 overlaid at
// u64 stride 41 — odd stride => conflict-free LDS.64/STS.64; overlap with stale z
// regions is safe because all z reads complete before first z1 store) = 43008B;
// ss float[128*11] = 5632B.  Total 48640B -> 4 blocks/SM (regs=128 target).
#define ZROW 21
#define SMEM_BYTES (128 * ZROW * 16 + 128 * 11 * 4)
#define PF_DIST 592   // one full wave (148 SMs * 4 blocks)

__global__ __launch_bounds__(128, 4)
void gnn_kernel(const float* __restrict__ x, const float* __restrict__ z,
                const float* __restrict__ y, float* __restrict__ out) {
    extern __shared__ float4 sm4[];
    float4* buf = sm4;
    float*  ss  = (float*)(sm4 + 128 * ZROW);
    u64*    z1b = (u64*)sm4;            // z1 overlay; row stride 41 u64

    const int t = threadIdx.x;
    const int blk = blockIdx.x;

    // ---- Phase 1: stage x coalesced into [128][11] float4 ----
    const float4* xg = (const float4*)x + (long long)blk * 1280;
#pragma unroll
    for (int k = 0; k < 10; k++) {
        const int i4 = t + k * 128;
        buf[(i4 / 10) * 11 + (i4 % 10)] = xg[i4];
    }
    __syncthreads();

    // ---- Phase 2: encoder ring aggregation ----
    float t1[10], t2[10];
#pragma unroll
    for (int c = 0; c < 10; c++) {
        const float4 v = buf[t * 11 + c];
        t1[c] = v.y + v.z + v.w;
        t2[c] = v.x + v.y + v.z;
    }
    float agg[10];
#pragma unroll
    for (int j = 0; j < 10; j++) agg[j] = t1[(j + 9) % 10] + t2[j];
    __syncthreads();   // x reads done before z overwrites buf

    // ---- Phase 3: stage z coalesced into [128][21] float4 ----
    const float4* zg = (const float4*)z + (long long)blk * 2560;
#pragma unroll
    for (int k = 0; k < 20; k++) {
        const int i4 = t + k * 128;
        buf[(i4 / 20) * ZROW + (i4 % 20)] = zg[i4];
    }

    // ---- Cross-block L2 prefetch: pull tiles of block blk+PF_DIST into L2 ----
    // (L2 is chip-shared: the data is consumed by whichever SM runs that block.)
    {
        const int b2 = blk + PF_DIST;
        if (b2 < (int)gridDim.x) {
            const char* xB = (const char*)x + (long long)b2 * 20480;  // 160 lines
            const char* zB = (const char*)z + (long long)b2 * 40960;  // 320 lines
            const char* yB = (const char*)y + (long long)b2 * 20480;  // 160 lines
            pfL2(xB + t * 128);
            if (t < 32) pfL2(xB + (128 + t) * 128);
            pfL2(zB + t * 128);
            pfL2(zB + (t + 128) * 128);
            if (t < 64) pfL2(zB + (t + 256) * 128);
            pfL2(yB + t * 128);
            if (t < 32) pfL2(yB + (128 + t) * 128);
        }
    }
    __syncthreads();

    const float4* row = buf + t * ZROW;

    // ======== Stage A: zz[4j+f2] = (z1[j][2f2], z1[j][2f2+1]) pre-relu ========
    u64 zz[40];
#pragma unroll
    for (int j = 0; j < 10; j++) {
        const u64 ab = pk2(agg[j], agg[j]);
#pragma unroll
        for (int f2 = 0; f2 < 4; f2++)
            zz[4 * j + f2] = ffma2(ab, c_w.encRW[f2], c_w.encB[f2]);
    }
#pragma unroll 1
    for (int gh = 0; gh < 2; gh++) {
        u64 w[4][4];
#pragma unroll
        for (int gw = 0; gw < 4; gw++)
#pragma unroll
            for (int f2 = 0; f2 < 4; f2++) w[gw][f2] = c_w.encW[4 * gh + gw][f2];
#pragma unroll
        for (int j = 0; j < 10; j++) {
            const float4 zv = row[2 * j + gh];
            const float zsc[4] = {zv.x, zv.y, zv.z, zv.w};
#pragma unroll
            for (int gw = 0; gw < 4; gw++) {
                const u64 zb = pk2(zsc[gw], zsc[gw]);
#pragma unroll
                for (int f2 = 0; f2 < 4; f2++)
                    zz[4 * j + f2] = ffma2(zb, w[gw][f2], zz[4 * j + f2]);
            }
        }
    }
    __syncthreads();   // every thread done reading z before z1 overlay writes

    // relu + store z1 as packed b64 pairs at stride 41 (conflict-free)
    u64* myz1 = z1b + t * 41;
#pragma unroll
    for (int i = 0; i < 40; i++) {
        float a, b; upk2(zz[i], a, b);
        myz1[i] = pk2(fmaxf(a, 0.0f), fmaxf(b, 0.0f));
    }

    // ======== Stage B: z2[d] = relu(z1[d]@W1^T + (z1[d-1]+z1[d+1])@W2^T + prb) ====
    //          s[d] = z2[d]·drw
#pragma unroll
    for (int dh = 0; dh < 2; dh++) {
        u64 acc[20];
#pragma unroll
        for (int d5 = 0; d5 < 5; d5++)
#pragma unroll
            for (int f2 = 0; f2 < 4; f2++) acc[4 * d5 + f2] = c_w.predB[f2];

#pragma unroll 1
        for (int p = 0; p < 4; p++) {       // g-pair (2p, 2p+1)
            u64 w1lo[4], w1hi[4], w2lo[4], w2hi[4];
#pragma unroll
            for (int f2 = 0; f2 < 4; f2++) {
                w1lo[f2] = c_w.W1[2 * p][f2];
                w1hi[f2] = c_w.W1[2 * p + 1][f2];
                w2lo[f2] = c_w.W2[2 * p][f2];
                w2hi[f2] = c_w.W2[2 * p + 1][f2];
            }
            u64 zr[7];
#pragma unroll
            for (int k = 0; k < 7; k++)
                zr[k] = myz1[4 * ((dh * 5 + k + 9) % 10) + p];
#pragma unroll
            for (int d5 = 0; d5 < 5; d5++) {
                const u64 zd = zr[d5 + 1];
                const u64 up = add2(zr[d5], zr[d5 + 2]);
                float zl, zh, ul, uh;
                upk2(zd, zl, zh); upk2(up, ul, uh);
                const u64 bzl = pk2(zl, zl), bzh = pk2(zh, zh);
                const u64 bul = pk2(ul, ul), buh = pk2(uh, uh);
#pragma unroll
                for (int f2 = 0; f2 < 4; f2++) {
                    u64 a = acc[4 * d5 + f2];
                    a = ffma2(bzl, w1lo[f2], a);
                    a = ffma2(bzh, w1hi[f2], a);
                    a = ffma2(bul, w2lo[f2], a);
                    a = ffma2(buh, w2hi[f2], a);
                    acc[4 * d5 + f2] = a;
                }
            }
        }
        // relu + dot with dec_rel_w -> s[d]  (ss is a separate region: no race)
#pragma unroll
        for (int d5 = 0; d5 < 5; d5++) {
            float f0, f1, f2v, f3, f4v, f5, f6, f7;
            upk2(acc[4 * d5 + 0], f0, f1);
            upk2(acc[4 * d5 + 1], f2v, f3);
            upk2(acc[4 * d5 + 2], f4v, f5);
            upk2(acc[4 * d5 + 3], f6, f7);
            const float sd = fmaxf(f0, 0.0f) * c_w.drw[0] + fmaxf(f1, 0.0f) * c_w.drw[1]
                           + fmaxf(f2v, 0.0f) * c_w.drw[2] + fmaxf(f3, 0.0f) * c_w.drw[3]
                           + fmaxf(f4v, 0.0f) * c_w.drw[4] + fmaxf(f5, 0.0f) * c_w.drw[5]
                           + fmaxf(f6, 0.0f) * c_w.drw[6] + fmaxf(f7, 0.0f) * c_w.drw[7];
            ss[t * 11 + dh * 5 + d5] = sd;
        }
    }
    __syncthreads();

    // ---- Decoder/output: fully coalesced float4 y-load + out-store ----
    const float drbv   = c_w.dec2[0];
    const float drootv = c_w.dec2[1];
    const float4* yg = (const float4*)y + (long long)blk * 1280;
    float4* og = (float4*)out + (long long)blk * 1280;
#pragma unroll
    for (int p = 0; p < 10; p++) {
        const int n4 = t + p * 128;
        const int bl = n4 / 10, c = n4 % 10;
        const float sa = ss[bl * 11 + c];
        const float sb = ss[bl * 11 + ((c == 9) ? 0 : c + 1)];
        const float4 yv = yg[n4];
        float4 o;
        o.x = sa + drbv + yv.x * drootv;          // m=0
        o.y = sa + sb + drbv + yv.y * drootv;     // m=1
        o.z = sa + sb + drbv + yv.z * drootv;     // m=2
        o.w = sb + drbv + yv.w * drootv;          // m=3
        og[n4] = o;
    }
}

extern "C" void kernel_launch(void* const* d_in, const int* in_sizes, int n_in,
                              void* d_out, int out_size) {
    const float* x     = (const float*)d_in[0];
    const float* z     = (const float*)d_in[1];
    const float* y     = (const float*)d_in[2];
    const float* erw   = (const float*)d_in[3];
    const float* erb   = (const float*)d_in[4];
    const float* erow  = (const float*)d_in[5];
    const float* prw   = (const float*)d_in[6];
    const float* prb   = (const float*)d_in[7];
    const float* prow  = (const float*)d_in[8];
    const float* drw   = (const float*)d_in[9];
    const float* drb   = (const float*)d_in[10];
    const float* droot = (const float*)d_in[11];

    const int B = in_sizes[0] / 40;       // 524288
    const int blocks = B / 128;           // 4096

    cudaFuncSetAttribute(gnn_kernel, cudaFuncAttributeMaxDynamicSharedMemorySize, SMEM_BYTES);

    prep_kernel<<<1, 32>>>(erw, erb, erow, prw, prb, prow, drw, drb, droot);

    void* stage_ptr = nullptr;
    cudaGetSymbolAddress(&stage_ptr, g_stage);
    cudaMemcpyToSymbolAsync(c_w, stage_ptr, sizeof(CW), 0, cudaMemcpyDeviceToDevice);

    gnn_kernel<<<blocks, 128, SMEM_BYTES>>>(x, z, y, (float*)d_out);
}

// round 10
// speedup vs baseline: 1.3598x; 1.1434x over previous
#include <cuda_runtime.h>

// HN=10, ND=40, HF=8 (fixed). A_ENC: agg[j]=sum x[4j-3..4j+2 mod 40].
// A_PRED: agg2[d]=z1[d]+w*(z1[d-1]+z1[d+1]), w=exp(-1/9).
// A_DEC per grid i (m=i%4): m0:s[c]; m1,m2:s[c]+s[c+1]; m3:s[c+1]  (c=i/4, wrap mod 10)
//
// R10 = R5 compute core (per-element threads, constant-bank weights, stride-41 z1)
//       with 64-thread blocks (8 independent blocks/SM for DRAM phase smoothing)
//       and half-of-y preloaded into registers during stage B (tail-burst shift).

typedef unsigned long long u64;

__device__ __forceinline__ u64 pk2(float a, float b) {
    u64 r; asm("mov.b64 %0, {%1, %2};" : "=l"(r) : "f"(a), "f"(b)); return r;
}
__device__ __forceinline__ void upk2(u64 v, float& a, float& b) {
    asm("mov.b64 {%0, %1}, %2;" : "=f"(a), "=f"(b) : "l"(v));
}
__device__ __forceinline__ u64 ffma2(u64 a, u64 b, u64 c) {
    u64 d; asm("fma.rn.f32x2 %0, %1, %2, %3;" : "=l"(d) : "l"(a), "l"(b), "l"(c)); return d;
}
__device__ __forceinline__ u64 add2(u64 a, u64 b) {
    u64 d; asm("add.rn.f32x2 %0, %1, %2;" : "=l"(d) : "l"(a), "l"(b)); return d;
}

struct CW {
    u64 encW[8][4];   // [g][f2] = (enc_root_w[2f2][g], enc_root_w[2f2+1][g])
    u64 encRW[4];     // enc_rel_w pairs
    u64 encB[4];      // enc_rel_b pairs
    u64 W1[8][4];     // (pred_rel_w + pred_root_w) pairs
    u64 W2[8][4];     // (exp(-1/9) * pred_rel_w) pairs
    u64 predB[4];     // pred_rel_b pairs
    float drw[8];     // dec_rel_w
    float dec2[2];    // dec_rel_b, dec_root_w
};
__constant__ CW c_w;
__device__ CW g_stage;

__global__ void prep_kernel(const float* __restrict__ erw, const float* __restrict__ erb,
                            const float* __restrict__ erow,
                            const float* __restrict__ prw, const float* __restrict__ prb,
                            const float* __restrict__ prow,
                            const float* __restrict__ drw, const float* __restrict__ drb,
                            const float* __restrict__ droot) {
    const int t = threadIdx.x;
    const float wE = expf(-1.0f / 9.0f);
    if (t < 32) {
        const int g = t & 7, f2 = t >> 3;
        const int i0 = (2 * f2) * 8 + g;
        const int i1 = (2 * f2 + 1) * 8 + g;
        g_stage.encW[g][f2] = pk2(erow[i0], erow[i1]);
        g_stage.W1[g][f2]   = pk2(prw[i0] + prow[i0], prw[i1] + prow[i1]);
        g_stage.W2[g][f2]   = pk2(wE * prw[i0], wE * prw[i1]);
    }
    if (t < 4) {
        g_stage.encRW[t] = pk2(erw[2 * t], erw[2 * t + 1]);
        g_stage.encB[t]  = pk2(erb[2 * t], erb[2 * t + 1]);
        g_stage.predB[t] = pk2(prb[2 * t], prb[2 * t + 1]);
    }
    if (t < 8) g_stage.drw[t] = drw[t];
    if (t == 0) { g_stage.dec2[0] = drb[0]; g_stage.dec2[1] = droot[0]; }
}

// 64 elements per block. Shared: buf float4[64*21] (x transient as [64][11] f4,
// then z; z1 overlaid at u64 stride 41 — all z reads complete before first z1
// store, enforced by a barrier) = 21504B; ss float[64*11] = 2816B.
// Total 24320B -> 8 blocks/SM; 64thr*8blk*128regs = 65536 = full RF.
#define NTHR 64
#define ZROW 21
#define SMEM_BYTES (NTHR * ZROW * 16 + NTHR * 11 * 4)

__global__ __launch_bounds__(NTHR, 8)
void gnn_kernel(const float* __restrict__ x, const float* __restrict__ z,
                const float* __restrict__ y, float* __restrict__ out) {
    extern __shared__ float4 sm4[];
    float4* buf = sm4;
    float*  ss  = (float*)(sm4 + NTHR * ZROW);
    u64*    z1b = (u64*)sm4;            // z1 overlay; row stride 41 u64

    const int t = threadIdx.x;
    const int blk = blockIdx.x;

    // ---- Phase 1: stage x coalesced into [64][11] float4 ----
    const float4* xg = (const float4*)x + (long long)blk * 640;
#pragma unroll
    for (int k = 0; k < 10; k++) {
        const int i4 = t + k * NTHR;
        buf[(i4 / 10) * 11 + (i4 % 10)] = xg[i4];
    }
    __syncthreads();

    // ---- Phase 2: encoder ring aggregation ----
    float t1[10], t2[10];
#pragma unroll
    for (int c = 0; c < 10; c++) {
        const float4 v = buf[t * 11 + c];
        t1[c] = v.y + v.z + v.w;
        t2[c] = v.x + v.y + v.z;
    }
    float agg[10];
#pragma unroll
    for (int j = 0; j < 10; j++) agg[j] = t1[(j + 9) % 10] + t2[j];
    __syncthreads();   // x reads done before z overwrites buf

    // ---- Phase 3: stage z coalesced into [64][21] float4 ----
    const float4* zg = (const float4*)z + (long long)blk * 1280;
#pragma unroll
    for (int k = 0; k < 20; k++) {
        const int i4 = t + k * NTHR;
        buf[(i4 / 20) * ZROW + (i4 % 20)] = zg[i4];
    }
    __syncthreads();

    const float4* row = buf + t * ZROW;

    // ======== Stage A: zz[4j+f2] = (z1[j][2f2], z1[j][2f2+1]) pre-relu ========
    u64 zz[40];
#pragma unroll
    for (int j = 0; j < 10; j++) {
        const u64 ab = pk2(agg[j], agg[j]);
#pragma unroll
        for (int f2 = 0; f2 < 4; f2++)
            zz[4 * j + f2] = ffma2(ab, c_w.encRW[f2], c_w.encB[f2]);
    }
#pragma unroll 1
    for (int gh = 0; gh < 2; gh++) {
        u64 w[4][4];
#pragma unroll
        for (int gw = 0; gw < 4; gw++)
#pragma unroll
            for (int f2 = 0; f2 < 4; f2++) w[gw][f2] = c_w.encW[4 * gh + gw][f2];
#pragma unroll
        for (int j = 0; j < 10; j++) {
            const float4 zv = row[2 * j + gh];
            const float zsc[4] = {zv.x, zv.y, zv.z, zv.w};
#pragma unroll
            for (int gw = 0; gw < 4; gw++) {
                const u64 zb = pk2(zsc[gw], zsc[gw]);
#pragma unroll
                for (int f2 = 0; f2 < 4; f2++)
                    zz[4 * j + f2] = ffma2(zb, w[gw][f2], zz[4 * j + f2]);
            }
        }
    }
    __syncthreads();   // every thread done reading z before z1 overlay writes

    // relu + store z1 as packed b64 pairs at stride 41 (conflict-free LDS/STS.64)
    u64* myz1 = z1b + t * 41;
#pragma unroll
    for (int i = 0; i < 40; i++) {
        float a, b; upk2(zz[i], a, b);
        myz1[i] = pk2(fmaxf(a, 0.0f), fmaxf(b, 0.0f));
    }

    // ---- Preload first half of y for the decode pass (tail-burst shift).
    //      Issued here, consumed ~600 FMA2s later: latency fully hidden. ----
    const float4* yg = (const float4*)y + (long long)blk * 640;
    float4 yr[5];
#pragma unroll
    for (int p = 0; p < 5; p++) yr[p] = yg[t + p * NTHR];

    // ======== Stage B: z2[d] = relu(z1[d]@W1^T + (z1[d-1]+z1[d+1])@W2^T + prb) ====
    //          s[d] = z2[d]·drw
#pragma unroll
    for (int dh = 0; dh < 2; dh++) {
        u64 acc[20];
#pragma unroll
        for (int d5 = 0; d5 < 5; d5++)
#pragma unroll
            for (int f2 = 0; f2 < 4; f2++) acc[4 * d5 + f2] = c_w.predB[f2];

#pragma unroll 1
        for (int p = 0; p < 4; p++) {       // g-pair (2p, 2p+1)
            u64 w1lo[4], w1hi[4], w2lo[4], w2hi[4];
#pragma unroll
            for (int f2 = 0; f2 < 4; f2++) {
                w1lo[f2] = c_w.W1[2 * p][f2];
                w1hi[f2] = c_w.W1[2 * p + 1][f2];
                w2lo[f2] = c_w.W2[2 * p][f2];
                w2hi[f2] = c_w.W2[2 * p + 1][f2];
            }
            u64 zr[7];
#pragma unroll
            for (int k = 0; k < 7; k++)
                zr[k] = myz1[4 * ((dh * 5 + k + 9) % 10) + p];
#pragma unroll
            for (int d5 = 0; d5 < 5; d5++) {
                const u64 zd = zr[d5 + 1];
                const u64 up = add2(zr[d5], zr[d5 + 2]);
                float zl, zh, ul, uh;
                upk2(zd, zl, zh); upk2(up, ul, uh);
                const u64 bzl = pk2(zl, zl), bzh = pk2(zh, zh);
                const u64 bul = pk2(ul, ul), buh = pk2(uh, uh);
#pragma unroll
                for (int f2 = 0; f2 < 4; f2++) {
                    u64 a = acc[4 * d5 + f2];
                    a = ffma2(bzl, w1lo[f2], a);
                    a = ffma2(bzh, w1hi[f2], a);
                    a = ffma2(bul, w2lo[f2], a);
                    a = ffma2(buh, w2hi[f2], a);
                    acc[4 * d5 + f2] = a;
                }
            }
        }
        // relu + dot with dec_rel_w -> s[d]  (ss is a separate region: no race)
#pragma unroll
        for (int d5 = 0; d5 < 5; d5++) {
            float f0, f1, f2v, f3, f4v, f5, f6, f7;
            upk2(acc[4 * d5 + 0], f0, f1);
            upk2(acc[4 * d5 + 1], f2v, f3);
            upk2(acc[4 * d5 + 2], f4v, f5);
            upk2(acc[4 * d5 + 3], f6, f7);
            const float sd = fmaxf(f0, 0.0f) * c_w.drw[0] + fmaxf(f1, 0.0f) * c_w.drw[1]
                           + fmaxf(f2v, 0.0f) * c_w.drw[2] + fmaxf(f3, 0.0f) * c_w.drw[3]
                           + fmaxf(f4v, 0.0f) * c_w.drw[4] + fmaxf(f5, 0.0f) * c_w.drw[5]
                           + fmaxf(f6, 0.0f) * c_w.drw[6] + fmaxf(f7, 0.0f) * c_w.drw[7];
            ss[t * 11 + dh * 5 + d5] = sd;
        }
    }
    __syncthreads();

    // ---- Decoder/output: fully coalesced; first 5 chunks use preloaded y ----
    const float drbv   = c_w.dec2[0];
    const float drootv = c_w.dec2[1];
    float4* og = (float4*)out + (long long)blk * 640;
#pragma unroll
    for (int p = 0; p < 10; p++) {
        const int n4 = t + p * NTHR;
        const int bl = n4 / 10, c = n4 % 10;
        const float sa = ss[bl * 11 + c];
        const float sb = ss[bl * 11 + ((c == 9) ? 0 : c + 1)];
        const float4 yv = (p < 5) ? yr[p] : yg[n4];
        float4 o;
        o.x = sa + drbv + yv.x * drootv;          // m=0
        o.y = sa + sb + drbv + yv.y * drootv;     // m=1
        o.z = sa + sb + drbv + yv.z * drootv;     // m=2
        o.w = sb + drbv + yv.w * drootv;          // m=3
        og[n4] = o;
    }
}

extern "C" void kernel_launch(void* const* d_in, const int* in_sizes, int n_in,
                              void* d_out, int out_size) {
    const float* x     = (const float*)d_in[0];
    const float* z     = (const float*)d_in[1];
    const float* y     = (const float*)d_in[2];
    const float* erw   = (const float*)d_in[3];
    const float* erb   = (const float*)d_in[4];
    const float* erow  = (const float*)d_in[5];
    const float* prw   = (const float*)d_in[6];
    const float* prb   = (const float*)d_in[7];
    const float* prow  = (const float*)d_in[8];
    const float* drw   = (const float*)d_in[9];
    const float* drb   = (const float*)d_in[10];
    const float* droot = (const float*)d_in[11];

    const int B = in_sizes[0] / 40;       // 524288
    const int blocks = B / NTHR;          // 8192

    cudaFuncSetAttribute(gnn_kernel, cudaFuncAttributeMaxDynamicSharedMemorySize, SMEM_BYTES);

    prep_kernel<<<1, 32>>>(erw, erb, erow, prw, prb, prow, drw, drb, droot);

    void* stage_ptr = nullptr;
    cudaGetSymbolAddress(&stage_ptr, g_stage);
    cudaMemcpyToSymbolAsync(c_w, stage_ptr, sizeof(CW), 0, cudaMemcpyDeviceToDevice);

    gnn_kernel<<<blocks, NTHR, SMEM_BYTES>>>(x, z, y, (float*)d_out);
}

// round 12
// speedup vs baseline: 1.6489x; 1.2127x over previous
#include <cuda_runtime.h>
#include <cstdint>

// HN=10, ND=40, HF=8 (fixed). A_ENC: agg[j]=sum x[4j-3..4j+2 mod 40].
// A_PRED: agg2[d]=z1[d]+w*(z1[d-1]+z1[d+1]), w=exp(-1/9).
// A_DEC per grid i (m=i%4): m0:s[c]; m1,m2:s[c]+s[c+1]; m3:s[c+1]  (c=i/4, wrap mod 10)
//
// R12 = R11 with the uint32_t compile fix: R5 champion core + cp.async.cg
//       (LDGSTS) staging for x/z — one instruction per 16B, no register
//       round-trip, no LDG->STS scoreboard stalls.

typedef unsigned long long u64;
typedef unsigned int u32;

__device__ __forceinline__ u64 pk2(float a, float b) {
    u64 r; asm("mov.b64 %0, {%1, %2};" : "=l"(r) : "f"(a), "f"(b)); return r;
}
__device__ __forceinline__ void upk2(u64 v, float& a, float& b) {
    asm("mov.b64 {%0, %1}, %2;" : "=f"(a), "=f"(b) : "l"(v));
}
__device__ __forceinline__ u64 ffma2(u64 a, u64 b, u64 c) {
    u64 d; asm("fma.rn.f32x2 %0, %1, %2, %3;" : "=l"(d) : "l"(a), "l"(b), "l"(c)); return d;
}
__device__ __forceinline__ u64 add2(u64 a, u64 b) {
    u64 d; asm("add.rn.f32x2 %0, %1, %2;" : "=l"(d) : "l"(a), "l"(b)); return d;
}
__device__ __forceinline__ void cpa16(u32 daddr, const void* g) {
    asm volatile("cp.async.cg.shared.global [%0], [%1], 16;" :: "r"(daddr), "l"(g));
}
__device__ __forceinline__ void cpa_wait_all() {
    asm volatile("cp.async.commit_group;\n\tcp.async.wait_group 0;" ::: "memory");
}

struct CW {
    u64 encW[8][4];   // [g][f2] = (enc_root_w[2f2][g], enc_root_w[2f2+1][g])
    u64 encRW[4];     // enc_rel_w pairs
    u64 encB[4];      // enc_rel_b pairs
    u64 W1[8][4];     // (pred_rel_w + pred_root_w) pairs
    u64 W2[8][4];     // (exp(-1/9) * pred_rel_w) pairs
    u64 predB[4];     // pred_rel_b pairs
    float drw[8];     // dec_rel_w
    float dec2[2];    // dec_rel_b, dec_root_w
};
__constant__ CW c_w;
__device__ CW g_stage;

__global__ void prep_kernel(const float* __restrict__ erw, const float* __restrict__ erb,
                            const float* __restrict__ erow,
                            const float* __restrict__ prw, const float* __restrict__ prb,
                            const float* __restrict__ prow,
                            const float* __restrict__ drw, const float* __restrict__ drb,
                            const float* __restrict__ droot) {
    const int t = threadIdx.x;
    const float wE = expf(-1.0f / 9.0f);
    if (t < 32) {
        const int g = t & 7, f2 = t >> 3;
        const int i0 = (2 * f2) * 8 + g;
        const int i1 = (2 * f2 + 1) * 8 + g;
        g_stage.encW[g][f2] = pk2(erow[i0], erow[i1]);
        g_stage.W1[g][f2]   = pk2(prw[i0] + prow[i0], prw[i1] + prow[i1]);
        g_stage.W2[g][f2]   = pk2(wE * prw[i0], wE * prw[i1]);
    }
    if (t < 4) {
        g_stage.encRW[t] = pk2(erw[2 * t], erw[2 * t + 1]);
        g_stage.encB[t]  = pk2(erb[2 * t], erb[2 * t + 1]);
        g_stage.predB[t] = pk2(prb[2 * t], prb[2 * t + 1]);
    }
    if (t < 8) g_stage.drw[t] = drw[t];
    if (t == 0) { g_stage.dec2[0] = drb[0]; g_stage.dec2[1] = droot[0]; }
}

// Shared: buf float4[128*21] (x transient as [128][11] f4, then z; z1 overlaid at
// u64 stride 41 — odd stride => conflict-free LDS/STS.64; all z reads complete
// before the overlay writes) = 43008B; ss float[128*11] = 5632B.
// Total 48640B -> 4 blocks/SM at 128 regs (16 warps).
#define ZROW 21
#define SMEM_BYTES (128 * ZROW * 16 + 128 * 11 * 4)

__global__ __launch_bounds__(128, 4)
void gnn_kernel(const float* __restrict__ x, const float* __restrict__ z,
                const float* __restrict__ y, float* __restrict__ out) {
    extern __shared__ float4 sm4[];
    float4* buf = sm4;
    float*  ss  = (float*)(sm4 + 128 * ZROW);
    u64*    z1b = (u64*)sm4;            // z1 overlay; row stride 41 u64

    const int t = threadIdx.x;
    const int blk = blockIdx.x;
    const u32 sbase = (u32)__cvta_generic_to_shared(buf);

    // ---- Phase 1: stage x via cp.async.cg into [128][11] float4 ----
    const float4* xg = (const float4*)x + (long long)blk * 1280;
#pragma unroll
    for (int k = 0; k < 10; k++) {
        const int i4 = t + k * 128;
        cpa16(sbase + ((i4 / 10) * 11 + (i4 % 10)) * 16, xg + i4);
    }
    cpa_wait_all();
    __syncthreads();

    // ---- Phase 2: encoder ring aggregation ----
    float t1[10], t2[10];
#pragma unroll
    for (int c = 0; c < 10; c++) {
        const float4 v = buf[t * 11 + c];
        t1[c] = v.y + v.z + v.w;
        t2[c] = v.x + v.y + v.z;
    }
    float agg[10];
#pragma unroll
    for (int j = 0; j < 10; j++) agg[j] = t1[(j + 9) % 10] + t2[j];
    __syncthreads();   // x reads done before z overwrites buf

    // ---- Phase 3: stage z via cp.async.cg into [128][21] float4 ----
    const float4* zg = (const float4*)z + (long long)blk * 2560;
#pragma unroll
    for (int k = 0; k < 20; k++) {
        const int i4 = t + k * 128;
        cpa16(sbase + ((i4 / 20) * ZROW + (i4 % 20)) * 16, zg + i4);
    }
    cpa_wait_all();
    __syncthreads();

    const float4* row = buf + t * ZROW;

    // ======== Stage A: zz[4j+f2] = (z1[j][2f2], z1[j][2f2+1]) pre-relu ========
    u64 zz[40];
#pragma unroll
    for (int j = 0; j < 10; j++) {
        const u64 ab = pk2(agg[j], agg[j]);
#pragma unroll
        for (int f2 = 0; f2 < 4; f2++)
            zz[4 * j + f2] = ffma2(ab, c_w.encRW[f2], c_w.encB[f2]);
    }
#pragma unroll 1
    for (int gh = 0; gh < 2; gh++) {
        u64 w[4][4];
#pragma unroll
        for (int gw = 0; gw < 4; gw++)
#pragma unroll
            for (int f2 = 0; f2 < 4; f2++) w[gw][f2] = c_w.encW[4 * gh + gw][f2];
#pragma unroll
        for (int j = 0; j < 10; j++) {
            const float4 zv = row[2 * j + gh];
            const float zsc[4] = {zv.x, zv.y, zv.z, zv.w};
#pragma unroll
            for (int gw = 0; gw < 4; gw++) {
                const u64 zb = pk2(zsc[gw], zsc[gw]);
#pragma unroll
                for (int f2 = 0; f2 < 4; f2++)
                    zz[4 * j + f2] = ffma2(zb, w[gw][f2], zz[4 * j + f2]);
            }
        }
    }
    __syncthreads();   // every thread done reading z before z1 overlay writes

    // relu + store z1 as packed b64 pairs at stride 41 (conflict-free)
    u64* myz1 = z1b + t * 41;
#pragma unroll
    for (int i = 0; i < 40; i++) {
        float a, b; upk2(zz[i], a, b);
        myz1[i] = pk2(fmaxf(a, 0.0f), fmaxf(b, 0.0f));
    }

    // ======== Stage B: z2[d] = relu(z1[d]@W1^T + (z1[d-1]+z1[d+1])@W2^T + prb) ====
    //          s[d] = z2[d]·drw
#pragma unroll
    for (int dh = 0; dh < 2; dh++) {
        u64 acc[20];
#pragma unroll
        for (int d5 = 0; d5 < 5; d5++)
#pragma unroll
            for (int f2 = 0; f2 < 4; f2++) acc[4 * d5 + f2] = c_w.predB[f2];

#pragma unroll 1
        for (int p = 0; p < 4; p++) {       // g-pair (2p, 2p+1)
            u64 w1lo[4], w1hi[4], w2lo[4], w2hi[4];
#pragma unroll
            for (int f2 = 0; f2 < 4; f2++) {
                w1lo[f2] = c_w.W1[2 * p][f2];
                w1hi[f2] = c_w.W1[2 * p + 1][f2];
                w2lo[f2] = c_w.W2[2 * p][f2];
                w2hi[f2] = c_w.W2[2 * p + 1][f2];
            }
            u64 zr[7];
#pragma unroll
            for (int k = 0; k < 7; k++)
                zr[k] = myz1[4 * ((dh * 5 + k + 9) % 10) + p];
#pragma unroll
            for (int d5 = 0; d5 < 5; d5++) {
                const u64 zd = zr[d5 + 1];
                const u64 up = add2(zr[d5], zr[d5 + 2]);
                float zl, zh, ul, uh;
                upk2(zd, zl, zh); upk2(up, ul, uh);
                const u64 bzl = pk2(zl, zl), bzh = pk2(zh, zh);
                const u64 bul = pk2(ul, ul), buh = pk2(uh, uh);
#pragma unroll
                for (int f2 = 0; f2 < 4; f2++) {
                    u64 a = acc[4 * d5 + f2];
                    a = ffma2(bzl, w1lo[f2], a);
                    a = ffma2(bzh, w1hi[f2], a);
                    a = ffma2(bul, w2lo[f2], a);
                    a = ffma2(buh, w2hi[f2], a);
                    acc[4 * d5 + f2] = a;
                }
            }
        }
        // relu + dot with dec_rel_w -> s[d]  (ss is a separate region: no race)
#pragma unroll
        for (int d5 = 0; d5 < 5; d5++) {
            float f0, f1, f2v, f3, f4v, f5, f6, f7;
            upk2(acc[4 * d5 + 0], f0, f1);
            upk2(acc[4 * d5 + 1], f2v, f3);
            upk2(acc[4 * d5 + 2], f4v, f5);
            upk2(acc[4 * d5 + 3], f6, f7);
            const float sd = fmaxf(f0, 0.0f) * c_w.drw[0] + fmaxf(f1, 0.0f) * c_w.drw[1]
                           + fmaxf(f2v, 0.0f) * c_w.drw[2] + fmaxf(f3, 0.0f) * c_w.drw[3]
                           + fmaxf(f4v, 0.0f) * c_w.drw[4] + fmaxf(f5, 0.0f) * c_w.drw[5]
                           + fmaxf(f6, 0.0f) * c_w.drw[6] + fmaxf(f7, 0.0f) * c_w.drw[7];
            ss[t * 11 + dh * 5 + d5] = sd;
        }
    }
    __syncthreads();

    // ---- Decoder/output: fully coalesced float4 y-load + out-store ----
    const float drbv   = c_w.dec2[0];
    const float drootv = c_w.dec2[1];
    const float4* yg = (const float4*)y + (long long)blk * 1280;
    float4* og = (float4*)out + (long long)blk * 1280;
#pragma unroll
    for (int p = 0; p < 10; p++) {
        const int n4 = t + p * 128;
        const int bl = n4 / 10, c = n4 % 10;
        const float sa = ss[bl * 11 + c];
        const float sb = ss[bl * 11 + ((c == 9) ? 0 : c + 1)];
        const float4 yv = yg[n4];
        float4 o;
        o.x = sa + drbv + yv.x * drootv;          // m=0
        o.y = sa + sb + drbv + yv.y * drootv;     // m=1
        o.z = sa + sb + drbv + yv.z * drootv;     // m=2
        o.w = sb + drbv + yv.w * drootv;          // m=3
        og[n4] = o;
    }
}

extern "C" void kernel_launch(void* const* d_in, const int* in_sizes, int n_in,
                              void* d_out, int out_size) {
    const float* x     = (const float*)d_in[0];
    const float* z     = (const float*)d_in[1];
    const float* y     = (const float*)d_in[2];
    const float* erw   = (const float*)d_in[3];
    const float* erb   = (const float*)d_in[4];
    const float* erow  = (const float*)d_in[5];
    const float* prw   = (const float*)d_in[6];
    const float* prb   = (const float*)d_in[7];
    const float* prow  = (const float*)d_in[8];
    const float* drw   = (const float*)d_in[9];
    const float* drb   = (const float*)d_in[10];
    const float* droot = (const float*)d_in[11];

    const int B = in_sizes[0] / 40;       // 524288
    const int blocks = B / 128;           // 4096

    cudaFuncSetAttribute(gnn_kernel, cudaFuncAttributeMaxDynamicSharedMemorySize, SMEM_BYTES);

    prep_kernel<<<1, 32>>>(erw, erb, erow, prw, prb, prow, drw, drb, droot);

    void* stage_ptr = nullptr;
    cudaGetSymbolAddress(&stage_ptr, g_stage);
    cudaMemcpyToSymbolAsync(c_w, stage_ptr, sizeof(CW), 0, cudaMemcpyDeviceToDevice);

    gnn_kernel<<<blocks, 128, SMEM_BYTES>>>(x, z, y, (float*)d_out);
}